// round 10
// baseline (speedup 1.0000x reference)
#include <cuda_runtime.h>
#include <cstdint>

#define NP 200000
#define NA 100000
#define NI 8000
#define NF 30000
#define HD 256
#define NOUT 349
#define E_C 500000
#define E_W 400000
#define E_A 100000
#define E_T 300000

// ---------------- scratch (static device allocations, allowed) ----------------
__device__ float g_mp0[(size_t)NP * HD];   // m0: mean cites(p) raw
__device__ float g_mp1[(size_t)NP * HD];   // g1: mean writes(a@Wl1)
__device__ float g_mp6[(size_t)NP * HD];   // g6: mean rev_topic(f@Wl6)
__device__ float g_ma2[(size_t)NA * HD];   // ma2: mean rev_writes(p) raw
__device__ float g_ma4[(size_t)NA * HD];   // g4: mean rev_aff(i@Wl4)
__device__ float g_mi3[(size_t)NI * HD];   // mi3: mean aff(a) raw
__device__ float g_mf5[(size_t)NF * HD];   // mf5: mean topic(p) raw

__device__ float g_tA[(size_t)NA * HD];    // a @ Wl1
__device__ float g_tI[(size_t)NI * HD];    // i @ Wl4
__device__ float g_tF[(size_t)NF * HD];    // f @ Wl6

__device__ float g_pb[2][(size_t)NP * HD]; // ping-pong node features
__device__ float g_ab[2][(size_t)NA * HD];
__device__ float g_ib[2][(size_t)NI * HD];
__device__ float g_fb[2][(size_t)NF * HD];

__device__ float g_WrP[2 * HD * HD];       // combined Wr for paper (r0+r1+r6), per layer
__device__ float g_WrA[2 * HD * HD];       // combined Wr for author (r2+r4)
__device__ float g_bP[2 * HD];
__device__ float g_bA[2 * HD];

// CSR scratch: cnt doubles as cursor after scan
__device__ int g_cnt_c[NP];   __device__ int g_off_c[NP + 1];   __device__ int g_adj_c[E_C];
__device__ int g_cnt_w[NP];   __device__ int g_off_w[NP + 1];   __device__ int g_adj_w[E_W];
__device__ int g_cnt_rw[NA];  __device__ int g_off_rw[NA + 1];  __device__ int g_adj_rw[E_W];
__device__ int g_cnt_af[NI];  __device__ int g_off_af[NI + 1];  __device__ int g_adj_af[E_A];
__device__ int g_cnt_raf[NA]; __device__ int g_off_raf[NA + 1]; __device__ int g_adj_raf[E_A];
__device__ int g_cnt_t[NF];   __device__ int g_off_t[NF + 1];   __device__ int g_adj_t[E_T];
__device__ int g_cnt_rt[NP];  __device__ int g_off_rt[NP + 1];  __device__ int g_adj_rt[E_T];

// ---------------- small kernels ----------------
__global__ void hist_kernel(const int* __restrict__ dst, int E, int* cnt) {
    int i = blockIdx.x * blockDim.x + threadIdx.x;
    if (i < E) atomicAdd(&cnt[dst[i]], 1);
}

__global__ void scan_kernel(int* cnt, int n, int* offs) {
    __shared__ int sh[1024];
    int tid = threadIdx.x;
    int chunk = (n + 1023) >> 10;
    int beg = tid * chunk;
    int end = beg + chunk; if (end > n) end = n;
    int s = 0;
    for (int i = beg; i < end; i++) s += cnt[i];
    sh[tid] = s;
    __syncthreads();
    for (int d = 1; d < 1024; d <<= 1) {
        int t = (tid >= d) ? sh[tid - d] : 0;
        __syncthreads();
        sh[tid] += t;
        __syncthreads();
    }
    int run = sh[tid] - s;
    for (int i = beg; i < end; i++) {
        int c = cnt[i];
        offs[i] = run;
        cnt[i]  = run;
        run += c;
    }
    if (beg < n && end == n) offs[n] = run;
}

__global__ void fill_kernel(const int* __restrict__ src, const int* __restrict__ dst,
                            int E, int* cursor, int* __restrict__ adj) {
    int i = blockIdx.x * blockDim.x + threadIdx.x;
    if (i < E) {
        int p = atomicAdd(&cursor[dst[i]], 1);
        adj[p] = src[i];
    }
}

// mean aggregation: 64 threads per dst node (float4 per thread), 4 nodes per block
__global__ void gather_mean_kernel(const float* __restrict__ x,
                                   const int* __restrict__ offs,
                                   const int* __restrict__ adj,
                                   float* __restrict__ out, int n_dst) {
    int node = blockIdx.x * 4 + (threadIdx.x >> 6);
    int lane = threadIdx.x & 63;
    if (node >= n_dst) return;
    int beg = offs[node], end = offs[node + 1];
    float4 acc = make_float4(0.f, 0.f, 0.f, 0.f);
    int e = beg;
    for (; e + 1 < end; e += 2) {
        int s0 = adj[e], s1 = adj[e + 1];
        float4 v0 = ((const float4*)(x + (size_t)s0 * HD))[lane];
        float4 v1 = ((const float4*)(x + (size_t)s1 * HD))[lane];
        acc.x += v0.x + v1.x; acc.y += v0.y + v1.y;
        acc.z += v0.z + v1.z; acc.w += v0.w + v1.w;
    }
    if (e < end) {
        float4 v = ((const float4*)(x + (size_t)adj[e] * HD))[lane];
        acc.x += v.x; acc.y += v.y; acc.z += v.z; acc.w += v.w;
    }
    float inv = (end > beg) ? 1.f / (float)(end - beg) : 0.f;
    float4 r = make_float4(acc.x * inv, acc.y * inv, acc.z * inv, acc.w * inv);
    ((float4*)(out + (size_t)node * HD))[lane] = r;
}

__global__ void combine_kernel(const float* __restrict__ Wr, const float* __restrict__ bl,
                               float* __restrict__ WrP, float* __restrict__ WrA,
                               float* __restrict__ bP, float* __restrict__ bA) {
    int idx = blockIdx.x * blockDim.x + threadIdx.x;
    if (idx < 2 * HD * HD) {
        int l = idx / (HD * HD), j = idx % (HD * HD);
        const float* base = Wr + (size_t)l * 7 * HD * HD;
        WrP[idx] = base[0 * HD * HD + j] + base[1 * HD * HD + j] + base[6 * HD * HD + j];
        WrA[idx] = base[2 * HD * HD + j] + base[4 * HD * HD + j];
    }
    if (idx < 2 * HD) {
        int l = idx / HD, j = idx % HD;
        const float* bb = bl + (size_t)l * 7 * HD;
        bP[idx] = bb[0 * HD + j] + bb[1 * HD + j] + bb[6 * HD + j];
        bA[idx] = bb[2 * HD + j] + bb[4 * HD + j];
    }
}

// ---------------- tf32 tensor-core multi-part GEMM, cp.async 3-stage pipeline ----
// C[M,N] = act( sum_p A_p[M,256] @ W_p[256,N] + bias + add0 + add1 )
struct GemmArgs {
    const float* A0; const float* A1;
    const float* W0; const float* W1;
    const float* add0; const float* add1;
    const float* bias;
    float* C;
    int nparts, nadd, M, N, relu;
};

#define BM 128
#define BN 128
#define BKC 32
#define AP 36     // A smem pitch: bank = (4*gq + tig) -> bijective, conflict-free
#define BP 136    // B smem pitch: bank = (8*tig + gq) -> bijective, conflict-free
#define STAGES 3
#define SMEM_BYTES (STAGES * (BM * AP + BKC * BP) * 4)

__device__ __forceinline__ uint32_t tf32b(float x) {
    uint32_t u;
    asm("cvt.rna.tf32.f32 %0, %1;" : "=r"(u) : "f"(x));
    return u;
}

__device__ __forceinline__ void mma_tf32(float* c, const uint32_t* a, const uint32_t* b) {
    asm volatile(
        "mma.sync.aligned.m16n8k8.row.col.f32.tf32.tf32.f32 "
        "{%0,%1,%2,%3}, {%4,%5,%6,%7}, {%8,%9}, {%0,%1,%2,%3};\n"
        : "+f"(c[0]), "+f"(c[1]), "+f"(c[2]), "+f"(c[3])
        : "r"(a[0]), "r"(a[1]), "r"(a[2]), "r"(a[3]), "r"(b[0]), "r"(b[1]));
}

__device__ __forceinline__ void cp16(uint32_t dst, const void* src, bool pred) {
    int sz = pred ? 16 : 0;
    asm volatile("cp.async.cg.shared.global [%0], [%1], 16, %2;\n"
                 :: "r"(dst), "l"(src), "r"(sz));
}
__device__ __forceinline__ void cp4(uint32_t dst, const void* src, bool pred) {
    int sz = pred ? 4 : 0;
    asm volatile("cp.async.ca.shared.global [%0], [%1], 4, %2;\n"
                 :: "r"(dst), "l"(src), "r"(sz));
}
__device__ __forceinline__ void cpcommit() { asm volatile("cp.async.commit_group;" ::: "memory"); }
__device__ __forceinline__ void cpwait1()  { asm volatile("cp.async.wait_group 1;" ::: "memory"); }
__device__ __forceinline__ void cpwait0()  { asm volatile("cp.async.wait_group 0;" ::: "memory"); }

__device__ __forceinline__ void issue_chunk(
        const GemmArgs& g, int c, int stage, uint32_t sA, uint32_t sB,
        int bm, int bn, int tid, bool fastB) {
    int part = c >> 3;
    int k0 = (c & 7) * BKC;
    const float* A = (part == 0) ? g.A0 : g.A1;
    const float* W = (part == 0) ? g.W0 : g.W1;
    // A: 128 rows x 32 k, 16B chunks
    int ar = tid & 127, half = tid >> 7;
    bool aok = (bm + ar) < g.M;
    const float* ag = A + (size_t)(bm + ar) * HD + k0 + half * 16;
    uint32_t ad = sA + (uint32_t)(stage * BM * AP + ar * AP + half * 16) * 4;
#pragma unroll
    for (int i = 0; i < 4; i++) cp16(ad + i * 16, ag + i * 4, aok);
    // B: 32 k-rows x 128 n
    int kr = tid >> 3;
    int nb0 = (tid & 7) * 16;
    uint32_t bd = sB + (uint32_t)(stage * BKC * BP + kr * BP + nb0) * 4;
    if (fastB) {
        const float* wg = W + (size_t)(k0 + kr) * g.N + bn + nb0;
#pragma unroll
        for (int i = 0; i < 4; i++)
            cp16(bd + i * 16, wg + i * 4, (bn + nb0 + i * 4) < g.N);
    } else {
        const float* wg = W + (size_t)(k0 + kr) * g.N;
#pragma unroll
        for (int i = 0; i < 16; i++) {
            int col = bn + nb0 + i;
            cp4(bd + (uint32_t)i * 4, wg + col, col < g.N);
        }
    }
}

extern __shared__ float dynsmem[];

__global__ __launch_bounds__(256, 2) void gemm_tf32_kernel(GemmArgs g) {
    float* Asm = dynsmem;                          // STAGES * BM * AP
    float* Bsm = dynsmem + STAGES * BM * AP;       // STAGES * BKC * BP
    uint32_t sA = (uint32_t)__cvta_generic_to_shared(Asm);
    uint32_t sB = (uint32_t)__cvta_generic_to_shared(Bsm);

    int tid = threadIdx.x;
    int bm = blockIdx.y * BM;
    int bn = blockIdx.x * BN;
    int warp = tid >> 5, lane = tid & 31;
    int warp_m = warp >> 2;          // 0..1 -> 64 rows each
    int warp_n = warp & 3;           // 0..3 -> 32 cols each
    int gq = lane >> 2, tig = lane & 3;
    bool fastB = ((g.N & 3) == 0);

    float acc[4][4][4];
#pragma unroll
    for (int i = 0; i < 4; i++)
#pragma unroll
        for (int j = 0; j < 4; j++)
#pragma unroll
            for (int q = 0; q < 4; q++) acc[i][j][q] = 0.f;

    int nchunks = g.nparts * 8;   // always >= 8 >= STAGES-1

    issue_chunk(g, 0, 0, sA, sB, bm, bn, tid, fastB); cpcommit();
    issue_chunk(g, 1, 1, sA, sB, bm, bn, tid, fastB); cpcommit();

    for (int c = 0; c < nchunks; c++) {
        if (c + 1 < nchunks) cpwait1(); else cpwait0();
        __syncthreads();

        int st = c % STAGES;
        const float* As_ = Asm + st * BM * AP;
        const float* Bs_ = Bsm + st * BKC * BP;
#pragma unroll
        for (int ks = 0; ks < 4; ks++) {
            int kb = ks * 8;
            uint32_t afr[4][4];
#pragma unroll
            for (int i = 0; i < 4; i++) {
                int mb = warp_m * 64 + i * 16;
                afr[i][0] = tf32b(As_[(mb + gq) * AP + kb + tig]);
                afr[i][1] = tf32b(As_[(mb + gq + 8) * AP + kb + tig]);
                afr[i][2] = tf32b(As_[(mb + gq) * AP + kb + tig + 4]);
                afr[i][3] = tf32b(As_[(mb + gq + 8) * AP + kb + tig + 4]);
            }
            uint32_t bfr[4][2];
#pragma unroll
            for (int j = 0; j < 4; j++) {
                int nb = warp_n * 32 + j * 8;
                bfr[j][0] = tf32b(Bs_[(kb + tig) * BP + nb + gq]);
                bfr[j][1] = tf32b(Bs_[(kb + tig + 4) * BP + nb + gq]);
            }
#pragma unroll
            for (int i = 0; i < 4; i++)
#pragma unroll
                for (int j = 0; j < 4; j++)
                    mma_tf32(acc[i][j], afr[i], bfr[j]);
        }
        __syncthreads();

        if (c + 2 < nchunks) {
            issue_chunk(g, c + 2, (c + 2) % STAGES, sA, sB, bm, bn, tid, fastB);
            cpcommit();
        }
    }

    // ---- epilogue: addends + bias + relu + guarded store ----
#pragma unroll
    for (int i = 0; i < 4; i++) {
        int r0 = bm + warp_m * 64 + i * 16 + gq;
        int r1 = r0 + 8;
#pragma unroll
        for (int j = 0; j < 4; j++) {
            int c0 = bn + warp_n * 32 + j * 8 + tig * 2;
            bool c0ok = c0 < g.N, c1ok = (c0 + 1) < g.N;
            float bia0 = 0.f, bia1 = 0.f;
            if (g.bias) {
                if (c0ok) bia0 = g.bias[c0];
                if (c1ok) bia1 = g.bias[c0 + 1];
            }
            float v00 = acc[i][j][0] + bia0, v01 = acc[i][j][1] + bia1;
            float v10 = acc[i][j][2] + bia0, v11 = acc[i][j][3] + bia1;
            if (g.nadd > 0) {
                const float* a0p = g.add0;
                if (r0 < g.M) {
                    if (c0ok) v00 += a0p[(size_t)r0 * g.N + c0];
                    if (c1ok) v01 += a0p[(size_t)r0 * g.N + c0 + 1];
                }
                if (r1 < g.M) {
                    if (c0ok) v10 += a0p[(size_t)r1 * g.N + c0];
                    if (c1ok) v11 += a0p[(size_t)r1 * g.N + c0 + 1];
                }
            }
            if (g.nadd > 1) {
                const float* a1p = g.add1;
                if (r0 < g.M) {
                    if (c0ok) v00 += a1p[(size_t)r0 * g.N + c0];
                    if (c1ok) v01 += a1p[(size_t)r0 * g.N + c0 + 1];
                }
                if (r1 < g.M) {
                    if (c0ok) v10 += a1p[(size_t)r1 * g.N + c0];
                    if (c1ok) v11 += a1p[(size_t)r1 * g.N + c0 + 1];
                }
            }
            if (g.relu) {
                v00 = v00 > 0.f ? v00 : 0.f; v01 = v01 > 0.f ? v01 : 0.f;
                v10 = v10 > 0.f ? v10 : 0.f; v11 = v11 > 0.f ? v11 : 0.f;
            }
            if (r0 < g.M) {
                if (c0ok) g.C[(size_t)r0 * g.N + c0]     = v00;
                if (c1ok) g.C[(size_t)r0 * g.N + c0 + 1] = v01;
            }
            if (r1 < g.M) {
                if (c0ok) g.C[(size_t)r1 * g.N + c0]     = v10;
                if (c1ok) g.C[(size_t)r1 * g.N + c0 + 1] = v11;
            }
        }
    }
}

// ---------------- host ----------------
static inline int cdiv(int a, int b) { return (a + b - 1) / b; }

static void launch_gemm(int M, int N, int nparts,
                        const float* A0, const float* W0,
                        const float* A1, const float* W1,
                        int nadd, const float* add0, const float* add1,
                        const float* bias, float* C, int relu) {
    GemmArgs g;
    g.A0 = A0; g.A1 = A1; g.W0 = W0; g.W1 = W1;
    g.add0 = add0; g.add1 = add1;
    g.nparts = nparts; g.nadd = nadd; g.M = M; g.N = N;
    g.bias = bias; g.C = C; g.relu = relu;
    dim3 grid(cdiv(N, BN), cdiv(M, BM));
    gemm_tf32_kernel<<<grid, 256, SMEM_BYTES>>>(g);
}

extern "C" void kernel_launch(void* const* d_in, const int* in_sizes, int n_in,
                              void* d_out, int out_size) {
    const float* xp = (const float*)d_in[0];
    const float* xa = (const float*)d_in[1];
    const float* xi = (const float*)d_in[2];
    const float* xf = (const float*)d_in[3];
    const int* cites_src = (const int*)d_in[4];
    const int* cites_dst = (const int*)d_in[5];
    const int* writes_src = (const int*)d_in[6];
    const int* writes_dst = (const int*)d_in[7];
    const int* rwrites_src = (const int*)d_in[8];
    const int* rwrites_dst = (const int*)d_in[9];
    const int* aff_src = (const int*)d_in[10];
    const int* aff_dst = (const int*)d_in[11];
    const int* raff_src = (const int*)d_in[12];
    const int* raff_dst = (const int*)d_in[13];
    const int* topic_src = (const int*)d_in[14];
    const int* topic_dst = (const int*)d_in[15];
    const int* rtopic_src = (const int*)d_in[16];
    const int* rtopic_dst = (const int*)d_in[17];
    const float* Wl = (const float*)d_in[18];
    const float* bl = (const float*)d_in[19];
    const float* Wr = (const float*)d_in[20];
    const float* Wout = (const float*)d_in[21];
    const float* bout = (const float*)d_in[22];

    cudaFuncSetAttribute(gemm_tf32_kernel,
                         cudaFuncAttributeMaxDynamicSharedMemorySize, SMEM_BYTES);

    float *m0, *gg1, *gg6, *ma2, *gg4, *mi3, *mf5, *tA, *tI, *tF;
    float *pb, *ab, *ib, *fb, *WrP, *WrA, *bP, *bA;
    int *cnt_c, *off_c, *adj_c, *cnt_w, *off_w, *adj_w;
    int *cnt_rw, *off_rw, *adj_rw, *cnt_af, *off_af, *adj_af;
    int *cnt_raf, *off_raf, *adj_raf, *cnt_t, *off_t, *adj_t;
    int *cnt_rt, *off_rt, *adj_rt;
    cudaGetSymbolAddress((void**)&m0, g_mp0);
    cudaGetSymbolAddress((void**)&gg1, g_mp1);
    cudaGetSymbolAddress((void**)&gg6, g_mp6);
    cudaGetSymbolAddress((void**)&ma2, g_ma2);
    cudaGetSymbolAddress((void**)&gg4, g_ma4);
    cudaGetSymbolAddress((void**)&mi3, g_mi3);
    cudaGetSymbolAddress((void**)&mf5, g_mf5);
    cudaGetSymbolAddress((void**)&tA, g_tA);
    cudaGetSymbolAddress((void**)&tI, g_tI);
    cudaGetSymbolAddress((void**)&tF, g_tF);
    cudaGetSymbolAddress((void**)&pb, g_pb);
    cudaGetSymbolAddress((void**)&ab, g_ab);
    cudaGetSymbolAddress((void**)&ib, g_ib);
    cudaGetSymbolAddress((void**)&fb, g_fb);
    cudaGetSymbolAddress((void**)&WrP, g_WrP);
    cudaGetSymbolAddress((void**)&WrA, g_WrA);
    cudaGetSymbolAddress((void**)&bP, g_bP);
    cudaGetSymbolAddress((void**)&bA, g_bA);
    cudaGetSymbolAddress((void**)&cnt_c, g_cnt_c);
    cudaGetSymbolAddress((void**)&off_c, g_off_c);
    cudaGetSymbolAddress((void**)&adj_c, g_adj_c);
    cudaGetSymbolAddress((void**)&cnt_w, g_cnt_w);
    cudaGetSymbolAddress((void**)&off_w, g_off_w);
    cudaGetSymbolAddress((void**)&adj_w, g_adj_w);
    cudaGetSymbolAddress((void**)&cnt_rw, g_cnt_rw);
    cudaGetSymbolAddress((void**)&off_rw, g_off_rw);
    cudaGetSymbolAddress((void**)&adj_rw, g_adj_rw);
    cudaGetSymbolAddress((void**)&cnt_af, g_cnt_af);
    cudaGetSymbolAddress((void**)&off_af, g_off_af);
    cudaGetSymbolAddress((void**)&adj_af, g_adj_af);
    cudaGetSymbolAddress((void**)&cnt_raf, g_cnt_raf);
    cudaGetSymbolAddress((void**)&off_raf, g_off_raf);
    cudaGetSymbolAddress((void**)&adj_raf, g_adj_raf);
    cudaGetSymbolAddress((void**)&cnt_t, g_cnt_t);
    cudaGetSymbolAddress((void**)&off_t, g_off_t);
    cudaGetSymbolAddress((void**)&adj_t, g_adj_t);
    cudaGetSymbolAddress((void**)&cnt_rt, g_cnt_rt);
    cudaGetSymbolAddress((void**)&off_rt, g_off_rt);
    cudaGetSymbolAddress((void**)&adj_rt, g_adj_rt);

    float* pbuf[2] = { pb, pb + (size_t)NP * HD };
    float* abuf[2] = { ab, ab + (size_t)NA * HD };
    float* ibuf[2] = { ib, ib + (size_t)NI * HD };
    float* fbuf[2] = { fb, fb + (size_t)NF * HD };

    // ---- build CSR for all 7 relations (reused by both layers) ----
    struct Rel { const int* src; const int* dst; int E; int n_dst; int* cnt; int* off; int* adj; };
    Rel rels[7] = {
        { cites_src,   cites_dst,   E_C, NP, cnt_c,   off_c,   adj_c   },
        { writes_src,  writes_dst,  E_W, NP, cnt_w,   off_w,   adj_w   },
        { rwrites_src, rwrites_dst, E_W, NA, cnt_rw,  off_rw,  adj_rw  },
        { aff_src,     aff_dst,     E_A, NI, cnt_af,  off_af,  adj_af  },
        { raff_src,    raff_dst,    E_A, NA, cnt_raf, off_raf, adj_raf },
        { topic_src,   topic_dst,   E_T, NF, cnt_t,   off_t,   adj_t   },
        { rtopic_src,  rtopic_dst,  E_T, NP, cnt_rt,  off_rt,  adj_rt  },
    };
    for (int r = 0; r < 7; r++) {
        cudaMemsetAsync(rels[r].cnt, 0, (size_t)rels[r].n_dst * sizeof(int), 0);
        hist_kernel<<<cdiv(rels[r].E, 256), 256>>>(rels[r].dst, rels[r].E, rels[r].cnt);
        scan_kernel<<<1, 1024>>>(rels[r].cnt, rels[r].n_dst, rels[r].off);
        fill_kernel<<<cdiv(rels[r].E, 256), 256>>>(rels[r].src, rels[r].dst, rels[r].E,
                                                   rels[r].cnt, rels[r].adj);
    }

    combine_kernel<<<cdiv(2 * HD * HD, 256), 256>>>(Wr, bl, WrP, WrA, bP, bA);

    // ---- 2 SAGE layers (smart-side: transform small side first, gather after) ----
    const float* cp = xp; const float* ca = xa; const float* ci = xi; const float* cf = xf;
    for (int l = 0; l < 2; l++) {
        const size_t WSZ = (size_t)HD * HD;
        const float* WlL = Wl + (size_t)l * 7 * WSZ;
        const float* blL = bl + (size_t)l * 7 * HD;

        // src-side transforms (linearity: mean(x)@W == mean(x@W))
        launch_gemm(NA, HD, 1, ca, WlL + 1 * WSZ, 0, 0, 0, 0, 0, 0, tA, 0);
        launch_gemm(NF, HD, 1, cf, WlL + 6 * WSZ, 0, 0, 0, 0, 0, 0, tF, 0);
        launch_gemm(NI, HD, 1, ci, WlL + 4 * WSZ, 0, 0, 0, 0, 0, 0, tI, 0);

        // gathers
        gather_mean_kernel<<<cdiv(NP, 4), 256>>>(cp, off_c,   adj_c,   m0,  NP);  // raw
        gather_mean_kernel<<<cdiv(NP, 4), 256>>>(tA, off_w,   adj_w,   gg1, NP);  // transformed
        gather_mean_kernel<<<cdiv(NP, 4), 256>>>(tF, off_rt,  adj_rt,  gg6, NP);  // transformed
        gather_mean_kernel<<<cdiv(NA, 4), 256>>>(cp, off_rw,  adj_rw,  ma2, NA);  // raw
        gather_mean_kernel<<<cdiv(NA, 4), 256>>>(tI, off_raf, adj_raf, gg4, NA);  // transformed
        gather_mean_kernel<<<cdiv(NI, 4), 256>>>(ca, off_af,  adj_af,  mi3, NI);  // raw
        gather_mean_kernel<<<cdiv(NF, 4), 256>>>(cp, off_t,   adj_t,   mf5, NF);  // raw

        // output GEMMs
        // new_p = relu(m0@Wl0 + p@WrP + bP + g1 + g6)
        launch_gemm(NP, HD, 2, m0, WlL + 0 * WSZ, cp, WrP + (size_t)l * WSZ,
                    2, gg1, gg6, bP + (size_t)l * HD, pbuf[l], 1);
        // new_a = relu(ma2@Wl2 + a@WrA + bA + g4)
        launch_gemm(NA, HD, 2, ma2, WlL + 2 * WSZ, ca, WrA + (size_t)l * WSZ,
                    1, gg4, 0, bA + (size_t)l * HD, abuf[l], 1);
        // new_i = relu(mi3@Wl3 + i@Wr3 + bl3)
        launch_gemm(NI, HD, 2, mi3, WlL + 3 * WSZ, ci, Wr + ((size_t)l * 7 + 3) * WSZ,
                    0, 0, 0, blL + 3 * HD, ibuf[l], 1);
        // new_f = relu(mf5@Wl5 + f@Wr5 + bl5)
        launch_gemm(NF, HD, 2, mf5, WlL + 5 * WSZ, cf, Wr + ((size_t)l * 7 + 5) * WSZ,
                    0, 0, 0, blL + 5 * HD, fbuf[l], 1);

        cp = pbuf[l]; ca = abuf[l]; ci = ibuf[l]; cf = fbuf[l];
    }

    // ---- final projection: out = p @ W_out + b_out (N=349, 4B cp.async path) ----
    launch_gemm(NP, NOUT, 1, cp, Wout, 0, 0, 0, 0, 0, bout, (float*)d_out, 0);
}

// round 11
// speedup vs baseline: 1.2312x; 1.2312x over previous
#include <cuda_runtime.h>
#include <cstdint>

#define NP 200000
#define NA 100000
#define NI 8000
#define NF 30000
#define HD 256
#define NOUT 349
#define E_C 500000
#define E_W 400000
#define E_A 100000
#define E_T 300000

// ---------------- scratch (static device allocations, allowed) ----------------
__device__ float g_mp0[(size_t)NP * HD];   // m0: mean cites(p) raw
__device__ float g_mp1[(size_t)NP * HD];   // g1: mean writes(a@Wl1)
__device__ float g_mp6[(size_t)NP * HD];   // g6: mean rev_topic(f@Wl6)
__device__ float g_ma2[(size_t)NA * HD];   // ma2: mean rev_writes(p) raw
__device__ float g_ma4[(size_t)NA * HD];   // g4: mean rev_aff(i@Wl4)
__device__ float g_mi3[(size_t)NI * HD];   // mi3: mean aff(a) raw
__device__ float g_mf5[(size_t)NF * HD];   // mf5: mean topic(p) raw

__device__ float g_tA[(size_t)NA * HD];    // a @ Wl1
__device__ float g_tI[(size_t)NI * HD];    // i @ Wl4
__device__ float g_tF[(size_t)NF * HD];    // f @ Wl6

__device__ float g_pb[2][(size_t)NP * HD]; // ping-pong node features
__device__ float g_ab[2][(size_t)NA * HD];
__device__ float g_ib[2][(size_t)NI * HD];
__device__ float g_fb[2][(size_t)NF * HD];

__device__ float g_WrP[2 * HD * HD];       // combined Wr for paper (r0+r1+r6), per layer
__device__ float g_WrA[2 * HD * HD];       // combined Wr for author (r2+r4)
__device__ float g_bP[2 * HD];
__device__ float g_bA[2 * HD];

// CSR scratch: cnt doubles as cursor after scan
__device__ int g_cnt_c[NP];   __device__ int g_off_c[NP + 1];   __device__ int g_adj_c[E_C];
__device__ int g_cnt_w[NP];   __device__ int g_off_w[NP + 1];   __device__ int g_adj_w[E_W];
__device__ int g_cnt_rw[NA];  __device__ int g_off_rw[NA + 1];  __device__ int g_adj_rw[E_W];
__device__ int g_cnt_af[NI];  __device__ int g_off_af[NI + 1];  __device__ int g_adj_af[E_A];
__device__ int g_cnt_raf[NA]; __device__ int g_off_raf[NA + 1]; __device__ int g_adj_raf[E_A];
__device__ int g_cnt_t[NF];   __device__ int g_off_t[NF + 1];   __device__ int g_adj_t[E_T];
__device__ int g_cnt_rt[NP];  __device__ int g_off_rt[NP + 1];  __device__ int g_adj_rt[E_T];

// ---------------- small kernels ----------------
__global__ void hist_kernel(const int* __restrict__ dst, int E, int* cnt) {
    int i = blockIdx.x * blockDim.x + threadIdx.x;
    if (i < E) atomicAdd(&cnt[dst[i]], 1);
}

__global__ void scan_kernel(int* cnt, int n, int* offs) {
    __shared__ int sh[1024];
    int tid = threadIdx.x;
    int chunk = (n + 1023) >> 10;
    int beg = tid * chunk;
    int end = beg + chunk; if (end > n) end = n;
    int s = 0;
    for (int i = beg; i < end; i++) s += cnt[i];
    sh[tid] = s;
    __syncthreads();
    for (int d = 1; d < 1024; d <<= 1) {
        int t = (tid >= d) ? sh[tid - d] : 0;
        __syncthreads();
        sh[tid] += t;
        __syncthreads();
    }
    int run = sh[tid] - s;
    for (int i = beg; i < end; i++) {
        int c = cnt[i];
        offs[i] = run;
        cnt[i]  = run;
        run += c;
    }
    if (beg < n && end == n) offs[n] = run;
}

__global__ void fill_kernel(const int* __restrict__ src, const int* __restrict__ dst,
                            int E, int* cursor, int* __restrict__ adj) {
    int i = blockIdx.x * blockDim.x + threadIdx.x;
    if (i < E) {
        int p = atomicAdd(&cursor[dst[i]], 1);
        adj[p] = src[i];
    }
}

// mean aggregation: 64 threads per dst node (float4 per thread), 4 nodes per block
__global__ void gather_mean_kernel(const float* __restrict__ x,
                                   const int* __restrict__ offs,
                                   const int* __restrict__ adj,
                                   float* __restrict__ out, int n_dst) {
    int node = blockIdx.x * 4 + (threadIdx.x >> 6);
    int lane = threadIdx.x & 63;
    if (node >= n_dst) return;
    int beg = offs[node], end = offs[node + 1];
    float4 acc = make_float4(0.f, 0.f, 0.f, 0.f);
    int e = beg;
    for (; e + 1 < end; e += 2) {
        int s0 = adj[e], s1 = adj[e + 1];
        float4 v0 = ((const float4*)(x + (size_t)s0 * HD))[lane];
        float4 v1 = ((const float4*)(x + (size_t)s1 * HD))[lane];
        acc.x += v0.x + v1.x; acc.y += v0.y + v1.y;
        acc.z += v0.z + v1.z; acc.w += v0.w + v1.w;
    }
    if (e < end) {
        float4 v = ((const float4*)(x + (size_t)adj[e] * HD))[lane];
        acc.x += v.x; acc.y += v.y; acc.z += v.z; acc.w += v.w;
    }
    float inv = (end > beg) ? 1.f / (float)(end - beg) : 0.f;
    float4 r = make_float4(acc.x * inv, acc.y * inv, acc.z * inv, acc.w * inv);
    ((float4*)(out + (size_t)node * HD))[lane] = r;
}

__global__ void combine_kernel(const float* __restrict__ Wr, const float* __restrict__ bl,
                               float* __restrict__ WrP, float* __restrict__ WrA,
                               float* __restrict__ bP, float* __restrict__ bA) {
    int idx = blockIdx.x * blockDim.x + threadIdx.x;
    if (idx < 2 * HD * HD) {
        int l = idx / (HD * HD), j = idx % (HD * HD);
        const float* base = Wr + (size_t)l * 7 * HD * HD;
        WrP[idx] = base[0 * HD * HD + j] + base[1 * HD * HD + j] + base[6 * HD * HD + j];
        WrA[idx] = base[2 * HD * HD + j] + base[4 * HD * HD + j];
    }
    if (idx < 2 * HD) {
        int l = idx / HD, j = idx % HD;
        const float* bb = bl + (size_t)l * 7 * HD;
        bP[idx] = bb[0 * HD + j] + bb[1 * HD + j] + bb[6 * HD + j];
        bA[idx] = bb[2 * HD + j] + bb[4 * HD + j];
    }
}

// ---------------- tf32 tensor-core multi-part GEMM (R9 proven inner loop) ------
// C[M,N] = act( sum_p A_p[M,256] @ W_p[256,N] + bias + add0 + add1 )
struct GemmArgs {
    const float* A[2];
    const float* W[2];
    const float* add0; const float* add1;
    const float* bias;
    float* C;
    int nparts, nadd, M, N, relu;
};

__device__ __forceinline__ float to_tf32(float x) {
    uint32_t u;
    asm("cvt.rna.tf32.f32 %0, %1;" : "=r"(u) : "f"(x));
    return __uint_as_float(u);
}

__device__ __forceinline__ void mma_tf32(float* c, const uint32_t* a, const uint32_t* b) {
    asm volatile(
        "mma.sync.aligned.m16n8k8.row.col.f32.tf32.tf32.f32 "
        "{%0,%1,%2,%3}, {%4,%5,%6,%7}, {%8,%9}, {%0,%1,%2,%3};\n"
        : "+f"(c[0]), "+f"(c[1]), "+f"(c[2]), "+f"(c[3])
        : "r"(a[0]), "r"(a[1]), "r"(a[2]), "r"(a[3]), "r"(b[0]), "r"(b[1]));
}

#define BK 32
#define APITCH 136  // 136 % 32 == 8 -> fragment loads (bank = 8*tig + g) conflict-free

__global__ __launch_bounds__(256) void gemm_tf32_kernel(GemmArgs g) {
    __shared__ float As[BK][APITCH];  // k-major: As[k][m]
    __shared__ float Bs[BK][APITCH];  // k-major: Bs[k][n]

    int tid = threadIdx.x;
    int bm = blockIdx.y * 128;
    int bn = blockIdx.x * 128;
    int warp = tid >> 5, lane = tid & 31;
    int warp_m = warp >> 2;          // 0..1  -> 64 rows each
    int warp_n = warp & 3;           // 0..3  -> 32 cols each
    int gq = lane >> 2, tig = lane & 3;

    // A loader: thread covers row lm, k-halves of 16
    int lm = tid & 127;
    int lk = tid >> 7;               // 0/1 -> k base lk*16
    bool arow_ok = (bm + lm) < g.M;

    // B loader: thread covers 4 cols at nc, k rows kr, kr+8, kr+16, kr+24
    int nc = (tid & 31) * 4;
    int kr = tid >> 5;               // 0..7

    float acc[4][4][4];
#pragma unroll
    for (int i = 0; i < 4; i++)
#pragma unroll
        for (int j = 0; j < 4; j++)
#pragma unroll
            for (int q = 0; q < 4; q++) acc[i][j][q] = 0.f;

    for (int p = 0; p < g.nparts; p++) {
        const float* A = g.A[p];
        const float* W = g.W[p];
        for (int k0 = 0; k0 < HD; k0 += BK) {
            // ---- load A tile (transpose to k-major, cvt to tf32) ----
            const float* Arow = A + (size_t)(bm + lm) * HD + k0 + lk * 16;
#pragma unroll
            for (int i = 0; i < 4; i++) {
                float4 v = make_float4(0.f, 0.f, 0.f, 0.f);
                if (arow_ok) v = *(const float4*)(Arow + i * 4);
                int kk = lk * 16 + i * 4;
                As[kk + 0][lm] = to_tf32(v.x);
                As[kk + 1][lm] = to_tf32(v.y);
                As[kk + 2][lm] = to_tf32(v.z);
                As[kk + 3][lm] = to_tf32(v.w);
            }
            // ---- load B tile (k-major already; scalar loads: N=349 rows unaligned) ----
#pragma unroll
            for (int i = 0; i < 4; i++) {
                int krow = kr + i * 8;
                const float* Wp = W + (size_t)(k0 + krow) * g.N + bn + nc;
                float4 v;
                v.x = (bn + nc + 0 < g.N) ? Wp[0] : 0.f;
                v.y = (bn + nc + 1 < g.N) ? Wp[1] : 0.f;
                v.z = (bn + nc + 2 < g.N) ? Wp[2] : 0.f;
                v.w = (bn + nc + 3 < g.N) ? Wp[3] : 0.f;
                v.x = to_tf32(v.x); v.y = to_tf32(v.y);
                v.z = to_tf32(v.z); v.w = to_tf32(v.w);
                *(float4*)(&Bs[krow][nc]) = v;
            }
            __syncthreads();

            // ---- 4 k8-steps of m16n8k8 tf32 mma ----
#pragma unroll
            for (int ks = 0; ks < 4; ks++) {
                int kb = ks * 8;
                uint32_t afr[4][4];
#pragma unroll
                for (int i = 0; i < 4; i++) {
                    int mb = warp_m * 64 + i * 16;
                    afr[i][0] = __float_as_uint(As[kb + tig][mb + gq]);
                    afr[i][1] = __float_as_uint(As[kb + tig][mb + gq + 8]);
                    afr[i][2] = __float_as_uint(As[kb + tig + 4][mb + gq]);
                    afr[i][3] = __float_as_uint(As[kb + tig + 4][mb + gq + 8]);
                }
                uint32_t bfr[4][2];
#pragma unroll
                for (int j = 0; j < 4; j++) {
                    int nb = warp_n * 32 + j * 8;
                    bfr[j][0] = __float_as_uint(Bs[kb + tig][nb + gq]);
                    bfr[j][1] = __float_as_uint(Bs[kb + tig + 4][nb + gq]);
                }
#pragma unroll
                for (int i = 0; i < 4; i++)
#pragma unroll
                    for (int j = 0; j < 4; j++)
                        mma_tf32(acc[i][j], afr[i], bfr[j]);
            }
            __syncthreads();
        }
    }

    // ---- epilogue: addends + bias + relu + guarded store ----
#pragma unroll
    for (int i = 0; i < 4; i++) {
        int r0 = bm + warp_m * 64 + i * 16 + gq;
        int r1 = r0 + 8;
#pragma unroll
        for (int j = 0; j < 4; j++) {
            int c0 = bn + warp_n * 32 + j * 8 + tig * 2;
            bool c0ok = c0 < g.N, c1ok = (c0 + 1) < g.N;
            float bia0 = 0.f, bia1 = 0.f;
            if (g.bias) {
                if (c0ok) bia0 = g.bias[c0];
                if (c1ok) bia1 = g.bias[c0 + 1];
            }
            float v00 = acc[i][j][0] + bia0, v01 = acc[i][j][1] + bia1;
            float v10 = acc[i][j][2] + bia0, v11 = acc[i][j][3] + bia1;
            if (g.nadd > 0) {
                const float* a0p = g.add0;
                if (r0 < g.M) {
                    if (c0ok) v00 += a0p[(size_t)r0 * g.N + c0];
                    if (c1ok) v01 += a0p[(size_t)r0 * g.N + c0 + 1];
                }
                if (r1 < g.M) {
                    if (c0ok) v10 += a0p[(size_t)r1 * g.N + c0];
                    if (c1ok) v11 += a0p[(size_t)r1 * g.N + c0 + 1];
                }
            }
            if (g.nadd > 1) {
                const float* a1p = g.add1;
                if (r0 < g.M) {
                    if (c0ok) v00 += a1p[(size_t)r0 * g.N + c0];
                    if (c1ok) v01 += a1p[(size_t)r0 * g.N + c0 + 1];
                }
                if (r1 < g.M) {
                    if (c0ok) v10 += a1p[(size_t)r1 * g.N + c0];
                    if (c1ok) v11 += a1p[(size_t)r1 * g.N + c0 + 1];
                }
            }
            if (g.relu) {
                v00 = v00 > 0.f ? v00 : 0.f; v01 = v01 > 0.f ? v01 : 0.f;
                v10 = v10 > 0.f ? v10 : 0.f; v11 = v11 > 0.f ? v11 : 0.f;
            }
            if (r0 < g.M) {
                if (c0ok) g.C[(size_t)r0 * g.N + c0]     = v00;
                if (c1ok) g.C[(size_t)r0 * g.N + c0 + 1] = v01;
            }
            if (r1 < g.M) {
                if (c0ok) g.C[(size_t)r1 * g.N + c0]     = v10;
                if (c1ok) g.C[(size_t)r1 * g.N + c0 + 1] = v11;
            }
        }
    }
}

// ---------------- host ----------------
static inline int cdiv(int a, int b) { return (a + b - 1) / b; }

static void launch_gemm(int M, int N, int nparts,
                        const float* A0, const float* W0,
                        const float* A1, const float* W1,
                        int nadd, const float* add0, const float* add1,
                        const float* bias, float* C, int relu) {
    GemmArgs g;
    g.A[0] = A0; g.A[1] = A1; g.W[0] = W0; g.W[1] = W1;
    g.add0 = add0; g.add1 = add1;
    g.nparts = nparts; g.nadd = nadd; g.M = M; g.N = N;
    g.bias = bias; g.C = C; g.relu = relu;
    dim3 grid(cdiv(N, 128), cdiv(M, 128));
    gemm_tf32_kernel<<<grid, 256>>>(g);
}

extern "C" void kernel_launch(void* const* d_in, const int* in_sizes, int n_in,
                              void* d_out, int out_size) {
    const float* xp = (const float*)d_in[0];
    const float* xa = (const float*)d_in[1];
    const float* xi = (const float*)d_in[2];
    const float* xf = (const float*)d_in[3];
    const int* cites_src = (const int*)d_in[4];
    const int* cites_dst = (const int*)d_in[5];
    const int* writes_src = (const int*)d_in[6];
    const int* writes_dst = (const int*)d_in[7];
    const int* rwrites_src = (const int*)d_in[8];
    const int* rwrites_dst = (const int*)d_in[9];
    const int* aff_src = (const int*)d_in[10];
    const int* aff_dst = (const int*)d_in[11];
    const int* raff_src = (const int*)d_in[12];
    const int* raff_dst = (const int*)d_in[13];
    const int* topic_src = (const int*)d_in[14];
    const int* topic_dst = (const int*)d_in[15];
    const int* rtopic_src = (const int*)d_in[16];
    const int* rtopic_dst = (const int*)d_in[17];
    const float* Wl = (const float*)d_in[18];
    const float* bl = (const float*)d_in[19];
    const float* Wr = (const float*)d_in[20];
    const float* Wout = (const float*)d_in[21];
    const float* bout = (const float*)d_in[22];

    float *m0, *gg1, *gg6, *ma2, *gg4, *mi3, *mf5, *tA, *tI, *tF;
    float *pb, *ab, *ib, *fb, *WrP, *WrA, *bP, *bA;
    int *cnt_c, *off_c, *adj_c, *cnt_w, *off_w, *adj_w;
    int *cnt_rw, *off_rw, *adj_rw, *cnt_af, *off_af, *adj_af;
    int *cnt_raf, *off_raf, *adj_raf, *cnt_t, *off_t, *adj_t;
    int *cnt_rt, *off_rt, *adj_rt;
    cudaGetSymbolAddress((void**)&m0, g_mp0);
    cudaGetSymbolAddress((void**)&gg1, g_mp1);
    cudaGetSymbolAddress((void**)&gg6, g_mp6);
    cudaGetSymbolAddress((void**)&ma2, g_ma2);
    cudaGetSymbolAddress((void**)&gg4, g_ma4);
    cudaGetSymbolAddress((void**)&mi3, g_mi3);
    cudaGetSymbolAddress((void**)&mf5, g_mf5);
    cudaGetSymbolAddress((void**)&tA, g_tA);
    cudaGetSymbolAddress((void**)&tI, g_tI);
    cudaGetSymbolAddress((void**)&tF, g_tF);
    cudaGetSymbolAddress((void**)&pb, g_pb);
    cudaGetSymbolAddress((void**)&ab, g_ab);
    cudaGetSymbolAddress((void**)&ib, g_ib);
    cudaGetSymbolAddress((void**)&fb, g_fb);
    cudaGetSymbolAddress((void**)&WrP, g_WrP);
    cudaGetSymbolAddress((void**)&WrA, g_WrA);
    cudaGetSymbolAddress((void**)&bP, g_bP);
    cudaGetSymbolAddress((void**)&bA, g_bA);
    cudaGetSymbolAddress((void**)&cnt_c, g_cnt_c);
    cudaGetSymbolAddress((void**)&off_c, g_off_c);
    cudaGetSymbolAddress((void**)&adj_c, g_adj_c);
    cudaGetSymbolAddress((void**)&cnt_w, g_cnt_w);
    cudaGetSymbolAddress((void**)&off_w, g_off_w);
    cudaGetSymbolAddress((void**)&adj_w, g_adj_w);
    cudaGetSymbolAddress((void**)&cnt_rw, g_cnt_rw);
    cudaGetSymbolAddress((void**)&off_rw, g_off_rw);
    cudaGetSymbolAddress((void**)&adj_rw, g_adj_rw);
    cudaGetSymbolAddress((void**)&cnt_af, g_cnt_af);
    cudaGetSymbolAddress((void**)&off_af, g_off_af);
    cudaGetSymbolAddress((void**)&adj_af, g_adj_af);
    cudaGetSymbolAddress((void**)&cnt_raf, g_cnt_raf);
    cudaGetSymbolAddress((void**)&off_raf, g_off_raf);
    cudaGetSymbolAddress((void**)&adj_raf, g_adj_raf);
    cudaGetSymbolAddress((void**)&cnt_t, g_cnt_t);
    cudaGetSymbolAddress((void**)&off_t, g_off_t);
    cudaGetSymbolAddress((void**)&adj_t, g_adj_t);
    cudaGetSymbolAddress((void**)&cnt_rt, g_cnt_rt);
    cudaGetSymbolAddress((void**)&off_rt, g_off_rt);
    cudaGetSymbolAddress((void**)&adj_rt, g_adj_rt);

    float* pbuf[2] = { pb, pb + (size_t)NP * HD };
    float* abuf[2] = { ab, ab + (size_t)NA * HD };
    float* ibuf[2] = { ib, ib + (size_t)NI * HD };
    float* fbuf[2] = { fb, fb + (size_t)NF * HD };

    // ---- build CSR for all 7 relations (reused by both layers) ----
    struct Rel { const int* src; const int* dst; int E; int n_dst; int* cnt; int* off; int* adj; };
    Rel rels[7] = {
        { cites_src,   cites_dst,   E_C, NP, cnt_c,   off_c,   adj_c   },
        { writes_src,  writes_dst,  E_W, NP, cnt_w,   off_w,   adj_w   },
        { rwrites_src, rwrites_dst, E_W, NA, cnt_rw,  off_rw,  adj_rw  },
        { aff_src,     aff_dst,     E_A, NI, cnt_af,  off_af,  adj_af  },
        { raff_src,    raff_dst,    E_A, NA, cnt_raf, off_raf, adj_raf },
        { topic_src,   topic_dst,   E_T, NF, cnt_t,   off_t,   adj_t   },
        { rtopic_src,  rtopic_dst,  E_T, NP, cnt_rt,  off_rt,  adj_rt  },
    };
    for (int r = 0; r < 7; r++) {
        cudaMemsetAsync(rels[r].cnt, 0, (size_t)rels[r].n_dst * sizeof(int), 0);
        hist_kernel<<<cdiv(rels[r].E, 256), 256>>>(rels[r].dst, rels[r].E, rels[r].cnt);
        scan_kernel<<<1, 1024>>>(rels[r].cnt, rels[r].n_dst, rels[r].off);
        fill_kernel<<<cdiv(rels[r].E, 256), 256>>>(rels[r].src, rels[r].dst, rels[r].E,
                                                   rels[r].cnt, rels[r].adj);
    }

    combine_kernel<<<cdiv(2 * HD * HD, 256), 256>>>(Wr, bl, WrP, WrA, bP, bA);

    // ---- 2 SAGE layers (smart-side: transform small side first, gather after) ----
    const float* cp = xp; const float* ca = xa; const float* ci = xi; const float* cf = xf;
    for (int l = 0; l < 2; l++) {
        const size_t WSZ = (size_t)HD * HD;
        const float* WlL = Wl + (size_t)l * 7 * WSZ;
        const float* blL = bl + (size_t)l * 7 * HD;

        // src-side transforms (linearity: mean(x)@W == mean(x@W))
        launch_gemm(NA, HD, 1, ca, WlL + 1 * WSZ, 0, 0, 0, 0, 0, 0, tA, 0);
        launch_gemm(NF, HD, 1, cf, WlL + 6 * WSZ, 0, 0, 0, 0, 0, 0, tF, 0);
        launch_gemm(NI, HD, 1, ci, WlL + 4 * WSZ, 0, 0, 0, 0, 0, 0, tI, 0);

        // gathers
        gather_mean_kernel<<<cdiv(NP, 4), 256>>>(cp, off_c,   adj_c,   m0,  NP);  // raw
        gather_mean_kernel<<<cdiv(NP, 4), 256>>>(tA, off_w,   adj_w,   gg1, NP);  // transformed
        gather_mean_kernel<<<cdiv(NP, 4), 256>>>(tF, off_rt,  adj_rt,  gg6, NP);  // transformed
        gather_mean_kernel<<<cdiv(NA, 4), 256>>>(cp, off_rw,  adj_rw,  ma2, NA);  // raw
        gather_mean_kernel<<<cdiv(NA, 4), 256>>>(tI, off_raf, adj_raf, gg4, NA);  // transformed
        gather_mean_kernel<<<cdiv(NI, 4), 256>>>(ca, off_af,  adj_af,  mi3, NI);  // raw
        gather_mean_kernel<<<cdiv(NF, 4), 256>>>(cp, off_t,   adj_t,   mf5, NF);  // raw

        // output GEMMs
        // new_p = relu(m0@Wl0 + p@WrP + bP + g1 + g6)
        launch_gemm(NP, HD, 2, m0, WlL + 0 * WSZ, cp, WrP + (size_t)l * WSZ,
                    2, gg1, gg6, bP + (size_t)l * HD, pbuf[l], 1);
        // new_a = relu(ma2@Wl2 + a@WrA + bA + g4)
        launch_gemm(NA, HD, 2, ma2, WlL + 2 * WSZ, ca, WrA + (size_t)l * WSZ,
                    1, gg4, 0, bA + (size_t)l * HD, abuf[l], 1);
        // new_i = relu(mi3@Wl3 + i@Wr3 + bl3)
        launch_gemm(NI, HD, 2, mi3, WlL + 3 * WSZ, ci, Wr + ((size_t)l * 7 + 3) * WSZ,
                    0, 0, 0, blL + 3 * HD, ibuf[l], 1);
        // new_f = relu(mf5@Wl5 + f@Wr5 + bl5)
        launch_gemm(NF, HD, 2, mf5, WlL + 5 * WSZ, cf, Wr + ((size_t)l * 7 + 5) * WSZ,
                    0, 0, 0, blL + 5 * HD, fbuf[l], 1);

        cp = pbuf[l]; ca = abuf[l]; ci = ibuf[l]; cf = fbuf[l];
    }

    // ---- final projection: out = p @ W_out + b_out ----
    launch_gemm(NP, NOUT, 1, cp, Wout, 0, 0, 0, 0, 0, bout, (float*)d_out, 0);
}